// round 14
// baseline (speedup 1.0000x reference)
#include <cuda_runtime.h>
#include <cuda_bf16.h>
#include <cstdint>

#define NN 40000
#define NE 640000

typedef unsigned long long u64;

// ---- device scratch ----
__device__ __align__(128) float g_buf[NN * 64];
__device__ __align__(128) float h_buf[NN * 64];
__device__ __align__(128) uint2 bph_buf[2048];   // packed B frags, hi
__device__ __align__(128) uint2 bpl_buf[2048];   // packed B frags, lo
__device__ int g_rowptr[NN + 1];

#define ADD_F32X2(d, a) asm("add.rn.f32x2 %0, %0, %1;" : "+l"(d) : "l"(a))

// ---------------------------------------------------------------------------
// Fused prep kernel.
//  blocks [0, 313):   CSR row pointers from SORTED dst (lower_bound)
//  blocks [313, 377): per-output-column W chain: W123[:,n] = W1@(W2@W3[:,n]),
//                     packed (bf16 hi/lo) into mma B fragments.
// ---------------------------------------------------------------------------
__global__ void __launch_bounds__(128)
prep(const int* __restrict__ dst, const float* __restrict__ W1,
     const float* __restrict__ W2, const float* __restrict__ W3,
     uint2* __restrict__ BPH, uint2* __restrict__ BPL) {
    const int b = blockIdx.x, tid = threadIdx.x;

    if (b < 313) {                      // ---- rowptr part ----
        int n = b * 128 + tid;
        if (n > NN) return;
        int lo = 0, hi = NE;
        while (lo < hi) {
            int mid = (lo + hi) >> 1;
            if (dst[mid] < n) lo = mid + 1; else hi = mid;
        }
        g_rowptr[n] = lo;
        return;
    }

    // ---- W-chain part: one block per column n ----
    const int n = b - 313;              // 0..63
    __shared__ float v[128], u[128], w[128];

    v[tid] = __ldg(&W3[tid * 64 + n]);
    __syncthreads();

    {   // u = W2 @ v
        const float4* row = (const float4*)(W2 + tid * 128);
        float acc = 0.f;
        #pragma unroll
        for (int k = 0; k < 32; k++) {
            float4 a = __ldg(&row[k]);
            acc += a.x * v[4 * k] + a.y * v[4 * k + 1] +
                   a.z * v[4 * k + 2] + a.w * v[4 * k + 3];
        }
        u[tid] = acc;
    }
    __syncthreads();

    {   // w = W1 @ u
        const float4* row = (const float4*)(W1 + tid * 128);
        float acc = 0.f;
        #pragma unroll
        for (int k = 0; k < 32; k++) {
            float4 a = __ldg(&row[k]);
            acc += a.x * u[4 * k] + a.y * u[4 * k + 1] +
                   a.z * u[4 * k + 2] + a.w * u[4 * k + 3];
        }
        w[tid] = acc;
    }
    __syncthreads();

    if (tid < 32) {                     // pack this column's 32 frag entries
        int c = tid >> 2, tig = tid & 3;
        int k0 = c * 16 + 2 * tig;
        float x0 = w[k0], x1 = w[k0 + 1], x2 = w[k0 + 8], x3 = w[k0 + 9];

        __nv_bfloat162 h01 = __floats2bfloat162_rn(x0, x1);
        __nv_bfloat162 h23 = __floats2bfloat162_rn(x2, x3);
        float2 b01 = __bfloat1622float2(h01);
        float2 b23 = __bfloat1622float2(h23);
        __nv_bfloat162 l01 = __floats2bfloat162_rn(x0 - b01.x, x1 - b01.y);
        __nv_bfloat162 l23 = __floats2bfloat162_rn(x2 - b23.x, x3 - b23.y);

        int t = n >> 3, g = n & 7;
        int idx = (t * 8 + c) * 32 + g * 4 + tig;
        BPH[idx] = make_uint2(*(uint32_t*)&h01, *(uint32_t*)&h23);
        BPL[idx] = make_uint2(*(uint32_t*)&l01, *(uint32_t*)&l23);
    }
}

// ---------------------------------------------------------------------------
// HMMA GEMM: X[N,64] = F[N,128] @ W123[128,64] via mma.sync m16n8k16
// bf16 3-term split (AhBh + AlBh + AhBl), fp32 accumulate.
// ---------------------------------------------------------------------------
#define MMA_BF16(c0, c1, c2, c3, a0, a1, a2, a3, b0, b1)                     \
    asm volatile(                                                            \
        "mma.sync.aligned.m16n8k16.row.col.f32.bf16.bf16.f32 "               \
        "{%0,%1,%2,%3}, {%4,%5,%6,%7}, {%8,%9}, {%0,%1,%2,%3};"              \
        : "+f"(c0), "+f"(c1), "+f"(c2), "+f"(c3)                             \
        : "r"(a0), "r"(a1), "r"(a2), "r"(a3), "r"(b0), "r"(b1))

__device__ __forceinline__ void split2(float2 v, uint32_t& h, uint32_t& l) {
    __nv_bfloat162 hh = __floats2bfloat162_rn(v.x, v.y);
    float2 b = __bfloat1622float2(hh);
    __nv_bfloat162 ll = __floats2bfloat162_rn(v.x - b.x, v.y - b.y);
    h = *(uint32_t*)&hh; l = *(uint32_t*)&ll;
}

__global__ void __launch_bounds__(256)
gemm_mma(const float* __restrict__ F, const uint2* __restrict__ BPH,
         const uint2* __restrict__ BPL, float* __restrict__ G) {
    __shared__ uint2 sBh[2048];
    __shared__ uint2 sBl[2048];
    const int tid = threadIdx.x;

    {   // Stage packed B frags (32KB) — uint4 copies
        const uint4* sh = (const uint4*)BPH;
        const uint4* sl = (const uint4*)BPL;
        uint4* dh = (uint4*)sBh; uint4* dl = (uint4*)sBl;
        #pragma unroll
        for (int i = tid; i < 1024; i += 256) { dh[i] = sh[i]; dl[i] = sl[i]; }
    }
    __syncthreads();

    const int warp = tid >> 5, lane = tid & 31;
    const int g = lane >> 2, tig = lane & 3;
    const int rowBase = blockIdx.x * 128 + warp * 16;
    const int rlo = min(rowBase + g,     NN - 1);
    const int rhi = min(rowBase + g + 8, NN - 1);
    const float2* flo = (const float2*)(F + (size_t)rlo * 128);
    const float2* fhi = (const float2*)(F + (size_t)rhi * 128);

    float acc[8][4];
    #pragma unroll
    for (int t = 0; t < 8; t++)
        #pragma unroll
        for (int j = 0; j < 4; j++) acc[t][j] = 0.f;

    #pragma unroll
    for (int c = 0; c < 8; c++) {
        float2 v0 = __ldg(&flo[c * 8 + tig]);
        float2 v1 = __ldg(&fhi[c * 8 + tig]);
        float2 v2 = __ldg(&flo[c * 8 + tig + 4]);
        float2 v3 = __ldg(&fhi[c * 8 + tig + 4]);
        uint32_t ah0, ah1, ah2, ah3, al0, al1, al2, al3;
        split2(v0, ah0, al0); split2(v1, ah1, al1);
        split2(v2, ah2, al2); split2(v3, ah3, al3);

        #pragma unroll
        for (int t = 0; t < 8; t++) {
            uint2 bh = sBh[(t * 8 + c) * 32 + lane];
            uint2 bl = sBl[(t * 8 + c) * 32 + lane];
            MMA_BF16(acc[t][0], acc[t][1], acc[t][2], acc[t][3],
                     ah0, ah1, ah2, ah3, bh.x, bh.y);
            MMA_BF16(acc[t][0], acc[t][1], acc[t][2], acc[t][3],
                     al0, al1, al2, al3, bh.x, bh.y);
            MMA_BF16(acc[t][0], acc[t][1], acc[t][2], acc[t][3],
                     ah0, ah1, ah2, ah3, bl.x, bl.y);
        }
    }

    const int rA = rowBase + g, rB = rowBase + g + 8;
    #pragma unroll
    for (int t = 0; t < 8; t++) {
        int col = t * 8 + 2 * tig;
        if (rA < NN)
            *(float2*)(G + (size_t)rA * 64 + col) = make_float2(acc[t][0], acc[t][1]);
        if (rB < NN)
            *(float2*)(G + (size_t)rB * 64 + col) = make_float2(acc[t][2], acc[t][3]);
    }
}

// ---------------------------------------------------------------------------
// Segment sum (width 64): one warp per node (R8 structure — 40K warps,
// regs~32, MLP=4, float2 lanes), with a leaner issue stream:
//  - uniform int4 index loads (broadcast; replaces coalesced load + SHFLs)
//  - packed add.rn.f32x2 accumulation (half the add instructions)
// Memory traffic, warp count, reg budget, occupancy: unchanged vs R8.
// ---------------------------------------------------------------------------
__global__ void __launch_bounds__(256, 8)
segsum64(const float* __restrict__ G, const int* __restrict__ src,
         float* __restrict__ Out) {
    int gw = (blockIdx.x * 256 + threadIdx.x) >> 5;
    int lane = threadIdx.x & 31;
    if (gw >= NN) return;
    int s = g_rowptr[gw], e = g_rowptr[gw + 1];

    u64 a0 = 0, a1 = 0, a2 = 0, a3 = 0;
    int j = s;
    // scalar prologue to 16B-align the int4 index loads
    for (; j < e && (j & 3); j++) {
        int s0 = __ldg(&src[j]);
        u64 x = __ldg((const u64*)(G + (size_t)s0 * 64) + lane);
        ADD_F32X2(a0, x);
    }
    for (; j + 3 < e; j += 4) {
        int4 v = __ldg((const int4*)(src + j));   // uniform across lanes
        u64 x0 = __ldg((const u64*)(G + (size_t)v.x * 64) + lane);
        u64 x1 = __ldg((const u64*)(G + (size_t)v.y * 64) + lane);
        u64 x2 = __ldg((const u64*)(G + (size_t)v.z * 64) + lane);
        u64 x3 = __ldg((const u64*)(G + (size_t)v.w * 64) + lane);
        ADD_F32X2(a0, x0);
        ADD_F32X2(a1, x1);
        ADD_F32X2(a2, x2);
        ADD_F32X2(a3, x3);
    }
    for (; j < e; j++) {
        int s0 = __ldg(&src[j]);
        u64 x = __ldg((const u64*)(G + (size_t)s0 * 64) + lane);
        ADD_F32X2(a0, x);
    }
    ADD_F32X2(a0, a1);
    ADD_F32X2(a2, a3);
    ADD_F32X2(a0, a2);
    *((u64*)(Out + (size_t)gw * 64) + lane) = a0;
}

// ---------------------------------------------------------------------------
// Launch.  out = S^3 (F @ (W1 @ (W2 @ W3)))   — 5 kernels total
// ---------------------------------------------------------------------------
extern "C" void kernel_launch(void* const* d_in, const int* in_sizes, int n_in,
                              void* d_out, int out_size) {
    const int*   src  = (const int*)d_in[0];
    const int*   dst  = (const int*)d_in[1];
    const float* feat = (const float*)d_in[2];
    const float* W1   = (const float*)d_in[3];
    const float* W2   = (const float*)d_in[4];
    const float* W3   = (const float*)d_in[5];
    float* out = (float*)d_out;

    float *gb, *hb; uint2 *bph, *bpl;
    cudaGetSymbolAddress((void**)&gb,  g_buf);
    cudaGetSymbolAddress((void**)&hb,  h_buf);
    cudaGetSymbolAddress((void**)&bph, bph_buf);
    cudaGetSymbolAddress((void**)&bpl, bpl_buf);

    const int GEMM_BLOCKS = (NN + 127) / 128;  // 313
    const int SEG_BLOCKS  = NN / 8;            // 5000 (8 warps/block)

    // rowptr (313 blocks) + W-chain/pack (64 blocks), fused
    prep<<<313 + 64, 128>>>(dst, W1, W2, W3, bph, bpl);

    // X = F @ W123 (HMMA, bf16 split)
    gemm_mma<<<GEMM_BLOCKS, 256>>>(feat, bph, bpl, gb);

    // out = S^3 X
    segsum64<<<SEG_BLOCKS, 256>>>(gb, src, hb);
    segsum64<<<SEG_BLOCKS, 256>>>(hb, src, gb);
    segsum64<<<SEG_BLOCKS, 256>>>(gb, src, out);
}

// round 15
// speedup vs baseline: 1.0778x; 1.0778x over previous
#include <cuda_runtime.h>
#include <cuda_bf16.h>
#include <cstdint>

#define NN 40000
#define NE 640000

// ---- device scratch ----
__device__ __align__(128) float g_buf[NN * 64];
__device__ __align__(128) float h_buf[NN * 64];
__device__ __align__(128) uint2 bph_buf[2048];   // packed B frags, hi
__device__ __align__(128) uint2 bpl_buf[2048];   // packed B frags, lo
__device__ int g_rowptr[NN + 1];

// ---------------------------------------------------------------------------
// Fused prep kernel.
//  blocks [0, 313):   CSR row pointers from SORTED dst (lower_bound)
//  blocks [313, 377): per-output-column W chain: W123[:,n] = W1@(W2@W3[:,n]),
//                     packed (bf16 hi/lo) into mma B fragments.
// ---------------------------------------------------------------------------
__global__ void __launch_bounds__(128)
prep(const int* __restrict__ dst, const float* __restrict__ W1,
     const float* __restrict__ W2, const float* __restrict__ W3,
     uint2* __restrict__ BPH, uint2* __restrict__ BPL) {
    const int b = blockIdx.x, tid = threadIdx.x;

    if (b < 313) {                      // ---- rowptr part ----
        int n = b * 128 + tid;
        if (n > NN) return;
        int lo = 0, hi = NE;
        while (lo < hi) {
            int mid = (lo + hi) >> 1;
            if (dst[mid] < n) lo = mid + 1; else hi = mid;
        }
        g_rowptr[n] = lo;
        return;
    }

    // ---- W-chain part: one block per column n ----
    const int n = b - 313;              // 0..63
    __shared__ float v[128], u[128], w[128];

    v[tid] = __ldg(&W3[tid * 64 + n]);
    __syncthreads();

    {   // u = W2 @ v
        const float4* row = (const float4*)(W2 + tid * 128);
        float acc = 0.f;
        #pragma unroll
        for (int k = 0; k < 32; k++) {
            float4 a = __ldg(&row[k]);
            acc += a.x * v[4 * k] + a.y * v[4 * k + 1] +
                   a.z * v[4 * k + 2] + a.w * v[4 * k + 3];
        }
        u[tid] = acc;
    }
    __syncthreads();

    {   // w = W1 @ u
        const float4* row = (const float4*)(W1 + tid * 128);
        float acc = 0.f;
        #pragma unroll
        for (int k = 0; k < 32; k++) {
            float4 a = __ldg(&row[k]);
            acc += a.x * u[4 * k] + a.y * u[4 * k + 1] +
                   a.z * u[4 * k + 2] + a.w * u[4 * k + 3];
        }
        w[tid] = acc;
    }
    __syncthreads();

    if (tid < 32) {                     // pack this column's 32 frag entries
        int c = tid >> 2, tig = tid & 3;
        int k0 = c * 16 + 2 * tig;
        float x0 = w[k0], x1 = w[k0 + 1], x2 = w[k0 + 8], x3 = w[k0 + 9];

        __nv_bfloat162 h01 = __floats2bfloat162_rn(x0, x1);
        __nv_bfloat162 h23 = __floats2bfloat162_rn(x2, x3);
        float2 b01 = __bfloat1622float2(h01);
        float2 b23 = __bfloat1622float2(h23);
        __nv_bfloat162 l01 = __floats2bfloat162_rn(x0 - b01.x, x1 - b01.y);
        __nv_bfloat162 l23 = __floats2bfloat162_rn(x2 - b23.x, x3 - b23.y);

        int t = n >> 3, g = n & 7;
        int idx = (t * 8 + c) * 32 + g * 4 + tig;
        BPH[idx] = make_uint2(*(uint32_t*)&h01, *(uint32_t*)&h23);
        BPL[idx] = make_uint2(*(uint32_t*)&l01, *(uint32_t*)&l23);
    }
}

// ---------------------------------------------------------------------------
// HMMA GEMM: X[N,64] = F[N,128] @ W123[128,64] via mma.sync m16n8k16
// bf16 3-term split (AhBh + AlBh + AhBl), fp32 accumulate.
// ---------------------------------------------------------------------------
#define MMA_BF16(c0, c1, c2, c3, a0, a1, a2, a3, b0, b1)                     \
    asm volatile(                                                            \
        "mma.sync.aligned.m16n8k16.row.col.f32.bf16.bf16.f32 "               \
        "{%0,%1,%2,%3}, {%4,%5,%6,%7}, {%8,%9}, {%0,%1,%2,%3};"              \
        : "+f"(c0), "+f"(c1), "+f"(c2), "+f"(c3)                             \
        : "r"(a0), "r"(a1), "r"(a2), "r"(a3), "r"(b0), "r"(b1))

__device__ __forceinline__ void split2(float2 v, uint32_t& h, uint32_t& l) {
    __nv_bfloat162 hh = __floats2bfloat162_rn(v.x, v.y);
    float2 b = __bfloat1622float2(hh);
    __nv_bfloat162 ll = __floats2bfloat162_rn(v.x - b.x, v.y - b.y);
    h = *(uint32_t*)&hh; l = *(uint32_t*)&ll;
}

__global__ void __launch_bounds__(256)
gemm_mma(const float* __restrict__ F, const uint2* __restrict__ BPH,
         const uint2* __restrict__ BPL, float* __restrict__ G) {
    __shared__ uint2 sBh[2048];
    __shared__ uint2 sBl[2048];
    const int tid = threadIdx.x;

    {   // Stage packed B frags (32KB) — uint4 copies
        const uint4* sh = (const uint4*)BPH;
        const uint4* sl = (const uint4*)BPL;
        uint4* dh = (uint4*)sBh; uint4* dl = (uint4*)sBl;
        #pragma unroll
        for (int i = tid; i < 1024; i += 256) { dh[i] = sh[i]; dl[i] = sl[i]; }
    }
    __syncthreads();

    const int warp = tid >> 5, lane = tid & 31;
    const int g = lane >> 2, tig = lane & 3;
    const int rowBase = blockIdx.x * 128 + warp * 16;
    const int rlo = min(rowBase + g,     NN - 1);
    const int rhi = min(rowBase + g + 8, NN - 1);
    const float2* flo = (const float2*)(F + (size_t)rlo * 128);
    const float2* fhi = (const float2*)(F + (size_t)rhi * 128);

    float acc[8][4];
    #pragma unroll
    for (int t = 0; t < 8; t++)
        #pragma unroll
        for (int j = 0; j < 4; j++) acc[t][j] = 0.f;

    #pragma unroll
    for (int c = 0; c < 8; c++) {
        float2 v0 = __ldg(&flo[c * 8 + tig]);
        float2 v1 = __ldg(&fhi[c * 8 + tig]);
        float2 v2 = __ldg(&flo[c * 8 + tig + 4]);
        float2 v3 = __ldg(&fhi[c * 8 + tig + 4]);
        uint32_t ah0, ah1, ah2, ah3, al0, al1, al2, al3;
        split2(v0, ah0, al0); split2(v1, ah1, al1);
        split2(v2, ah2, al2); split2(v3, ah3, al3);

        #pragma unroll
        for (int t = 0; t < 8; t++) {
            uint2 bh = sBh[(t * 8 + c) * 32 + lane];
            uint2 bl = sBl[(t * 8 + c) * 32 + lane];
            MMA_BF16(acc[t][0], acc[t][1], acc[t][2], acc[t][3],
                     ah0, ah1, ah2, ah3, bh.x, bh.y);
            MMA_BF16(acc[t][0], acc[t][1], acc[t][2], acc[t][3],
                     al0, al1, al2, al3, bh.x, bh.y);
            MMA_BF16(acc[t][0], acc[t][1], acc[t][2], acc[t][3],
                     ah0, ah1, ah2, ah3, bl.x, bl.y);
        }
    }

    const int rA = rowBase + g, rB = rowBase + g + 8;
    #pragma unroll
    for (int t = 0; t < 8; t++) {
        int col = t * 8 + 2 * tig;
        if (rA < NN)
            *(float2*)(G + (size_t)rA * 64 + col) = make_float2(acc[t][0], acc[t][1]);
        if (rB < NN)
            *(float2*)(G + (size_t)rB * 64 + col) = make_float2(acc[t][2], acc[t][3]);
    }
}

// ---------------------------------------------------------------------------
// Segment sum (width 64): one warp per node, R8 inner loop verbatim
// (proven 19.3us; issue-stream cuts verified neutral in R14, structural
// changes verified harmful in R9-R12). One change vs R8: 128-thread blocks
// (4 warps) — finer block-retirement granularity so a single high-degree
// node holds 4 warp slots hostage instead of 8. Residency unchanged:
// launch_bounds(128,16) -> 64 warps/SM.
// ---------------------------------------------------------------------------
__global__ void __launch_bounds__(128, 16)
segsum64(const float* __restrict__ G, const int* __restrict__ src,
         float* __restrict__ Out) {
    int gw = (blockIdx.x * 128 + threadIdx.x) >> 5;
    int lane = threadIdx.x & 31;
    if (gw >= NN) return;
    int s = g_rowptr[gw], e = g_rowptr[gw + 1];

    float2 acc0 = make_float2(0, 0), acc1 = make_float2(0, 0);
    float2 acc2 = make_float2(0, 0), acc3 = make_float2(0, 0);
    for (int base = s; base < e; base += 32) {
        int cnt = min(32, e - base);
        int myidx = (base + lane < e) ? __ldg(&src[base + lane]) : 0;
        int j = 0;
        for (; j + 3 < cnt; j += 4) {
            int s0 = __shfl_sync(0xffffffffu, myidx, j);
            int s1 = __shfl_sync(0xffffffffu, myidx, j + 1);
            int s2 = __shfl_sync(0xffffffffu, myidx, j + 2);
            int s3 = __shfl_sync(0xffffffffu, myidx, j + 3);
            float2 x0 = __ldg((const float2*)(G + (size_t)s0 * 64) + lane);
            float2 x1 = __ldg((const float2*)(G + (size_t)s1 * 64) + lane);
            float2 x2 = __ldg((const float2*)(G + (size_t)s2 * 64) + lane);
            float2 x3 = __ldg((const float2*)(G + (size_t)s3 * 64) + lane);
            acc0.x += x0.x; acc0.y += x0.y;
            acc1.x += x1.x; acc1.y += x1.y;
            acc2.x += x2.x; acc2.y += x2.y;
            acc3.x += x3.x; acc3.y += x3.y;
        }
        for (; j < cnt; j++) {
            int s0 = __shfl_sync(0xffffffffu, myidx, j);
            float2 x0 = __ldg((const float2*)(G + (size_t)s0 * 64) + lane);
            acc0.x += x0.x; acc0.y += x0.y;
        }
    }
    float2 o = make_float2((acc0.x + acc1.x) + (acc2.x + acc3.x),
                           (acc0.y + acc1.y) + (acc2.y + acc3.y));
    *((float2*)(Out + (size_t)gw * 64) + lane) = o;
}

// ---------------------------------------------------------------------------
// Launch.  out = S^3 (F @ (W1 @ (W2 @ W3)))   — 5 kernels total
// ---------------------------------------------------------------------------
extern "C" void kernel_launch(void* const* d_in, const int* in_sizes, int n_in,
                              void* d_out, int out_size) {
    const int*   src  = (const int*)d_in[0];
    const int*   dst  = (const int*)d_in[1];
    const float* feat = (const float*)d_in[2];
    const float* W1   = (const float*)d_in[3];
    const float* W2   = (const float*)d_in[4];
    const float* W3   = (const float*)d_in[5];
    float* out = (float*)d_out;

    float *gb, *hb; uint2 *bph, *bpl;
    cudaGetSymbolAddress((void**)&gb,  g_buf);
    cudaGetSymbolAddress((void**)&hb,  h_buf);
    cudaGetSymbolAddress((void**)&bph, bph_buf);
    cudaGetSymbolAddress((void**)&bpl, bpl_buf);

    const int GEMM_BLOCKS = (NN + 127) / 128;  // 313
    const int SEG_BLOCKS  = NN / 4;            // 10000 (4 warps/block)

    // rowptr (313 blocks) + W-chain/pack (64 blocks), fused
    prep<<<313 + 64, 128>>>(dst, W1, W2, W3, bph, bpl);

    // X = F @ W123 (HMMA, bf16 split)
    gemm_mma<<<GEMM_BLOCKS, 256>>>(feat, bph, bpl, gb);

    // out = S^3 X
    segsum64<<<SEG_BLOCKS, 128>>>(gb, src, hb);
    segsum64<<<SEG_BLOCKS, 128>>>(hb, src, gb);
    segsum64<<<SEG_BLOCKS, 128>>>(gb, src, out);
}